// round 11
// baseline (speedup 1.0000x reference)
#include <cuda_runtime.h>
#include <cuda_fp16.h>
#include <cuda.h>
#include <cstdint>
#include <cstddef>

#define CHANNELS 1024
#define PIVOT 16384

// tcgen05/TMA are arch-SPECIFIC. The harness also compiles a non-'a'
// compute_103 PTX pass; give it a plain-CUDA fallback body.
#if defined(__CUDA_ARCH_FEAT_SM103_ALL) || defined(__CUDA_ARCH_FEAT_SM100_ALL) || defined(__CUDA_ARCH_SPECIFIC__)
#define HAS_TCGEN05 1
#else
#define HAS_TCGEN05 0
#endif

// ---------------- scratch (static device arrays are allowed) ----------
__device__ __align__(1024) __half Xh_g[(size_t)PIVOT * CHANNELS];        // 32 MB
__device__ __align__(1024) __half Wh_g[(size_t)CHANNELS * CHANNELS];     //  2 MB
__device__ __align__(1024) __half A2_g[(size_t)2 * PIVOT * CHANNELS];    // 64 MB

// ---------------- device helpers ----------------
__device__ __forceinline__ uint32_t smem_u32(const void* p) {
    uint32_t r;
    asm("{ .reg .u64 t; cvta.to.shared.u64 t, %1; cvt.u32.u64 %0, t; }" : "=r"(r) : "l"(p));
    return r;
}
__device__ __forceinline__ uint32_t elect_one() {
    uint32_t p;
    asm volatile("{ .reg .pred p; elect.sync _|p, 0xFFFFFFFF; selp.b32 %0, 1, 0, p; }" : "=r"(p));
    return p;
}
// SW128 K-major smem descriptor (layout=2, version=1, SBO=64, LBO=1)
__device__ __forceinline__ uint64_t make_desc(uint32_t addr) {
    const uint64_t base = (uint64_t(2) << 61) | (uint64_t(1) << 46)
                        | (uint64_t(64) << 32) | (uint64_t(1) << 16);
    return base | ((uint64_t)(addr >> 4) & 0x3FFF);
}

#if HAS_TCGEN05
__device__ __forceinline__ uint32_t ctarank() {
    uint32_t r; asm("mov.u32 %0, %%cluster_ctarank;" : "=r"(r)); return r;
}
#define TCG_ALLOC(smem_res, ncols) \
    asm volatile("tcgen05.alloc.cta_group::1.sync.aligned.shared::cta.b32 [%0], %1;" \
                 :: "r"(smem_res), "r"((uint32_t)(ncols)) : "memory")
#define TCG_RELINQ() \
    asm volatile("tcgen05.relinquish_alloc_permit.cta_group::1.sync.aligned;")
#define TCG_DEALLOC(tmem, ncols) \
    asm volatile("tcgen05.dealloc.cta_group::1.sync.aligned.b32 %0, %1;" \
                 :: "r"(tmem), "r"((uint32_t)(ncols)))
#define TCG_COMMIT(mbar) \
    asm volatile("tcgen05.commit.cta_group::1.mbarrier::arrive::one.shared::cluster.b64 [%0];" \
                 :: "r"(mbar) : "memory")
#define TCG_COMMIT_MC(mbar, mask) \
    asm volatile("tcgen05.commit.cta_group::1.mbarrier::arrive::one.shared::cluster.multicast::cluster.b64 [%0], %1;" \
                 :: "r"(mbar), "h"((uint16_t)(mask)) : "memory")
#define TCG_FENCE_AFTER()  asm volatile("tcgen05.fence::after_thread_sync;" ::: "memory")
#define TCG_FENCE_BEFORE() asm volatile("tcgen05.fence::before_thread_sync;" ::: "memory")
#define TCG_WAIT_LD()      asm volatile("tcgen05.wait::ld.sync.aligned;" ::: "memory")
#define FENCE_ASYNC()      asm volatile("fence.proxy.async.shared::cta;" ::: "memory")
#define MBAR_INIT(addr, cnt) \
    asm volatile("mbarrier.init.shared.b64 [%0], %1;" :: "r"(addr), "r"((uint32_t)(cnt)) : "memory")
#define MBAR_INVAL(addr) \
    asm volatile("mbarrier.inval.shared.b64 [%0];" :: "r"(addr) : "memory")
#define MBAR_EXPECT_TX(addr, bytes) \
    asm volatile("mbarrier.arrive.expect_tx.shared.b64 _, [%0], %1;" \
                 :: "r"(addr), "r"((uint32_t)(bytes)) : "memory")
#define CLUSTER_SYNC() do { \
    asm volatile("barrier.cluster.arrive.aligned;" ::: "memory"); \
    asm volatile("barrier.cluster.wait.aligned;"   ::: "memory"); } while (0)

// Sleep-hint wait (HW TRYWAIT, no hot poll)
__device__ __forceinline__ void mbar_wait(uint32_t addr, uint32_t parity) {
    asm volatile(
        "{\n\t.reg .pred P;\n\t"
        "W_%=:\n\t"
        "mbarrier.try_wait.parity.shared.b64 P, [%0], %1, 0x989680;\n\t"
        "@!P bra W_%=;\n\t}"
        :: "r"(addr), "r"(parity) : "memory");
}
// Multicast 2D TMA load: delivers data + complete_tx to same smem offset in
// every CTA whose bit is set in mask.
__device__ __forceinline__ void tma2d_mc(uint32_t dst, const void* map,
                                         int32_t cx, int32_t cy, uint32_t mbar,
                                         uint16_t mask) {
    asm volatile(
        "cp.async.bulk.tensor.2d.shared::cluster.global.tile.mbarrier::complete_tx::bytes.multicast::cluster "
        "[%0], [%1, {%2, %3}], [%4], %5;"
        :: "r"(dst), "l"(map), "r"(cx), "r"(cy), "r"(mbar), "h"(mask) : "memory");
}
__device__ __forceinline__ void mma_f16_ss(uint32_t d_tmem, uint64_t a_desc,
                                           uint64_t b_desc, uint32_t idesc, uint32_t en) {
    asm volatile(
        "{\n\t.reg .pred p;\n\t"
        "setp.ne.u32 p, %4, 0;\n\t"
        "tcgen05.mma.cta_group::1.kind::f16 [%0], %1, %2, %3, {%5,%5,%5,%5}, p;\n\t}"
        :: "r"(d_tmem), "l"(a_desc), "l"(b_desc), "r"(idesc), "r"(en), "r"(0u) : "memory");
}
#define TCG_LD_X32(r, addr) \
    asm volatile( \
        "tcgen05.ld.sync.aligned.32x32b.x32.b32 " \
        "{%0, %1, %2, %3, %4, %5, %6, %7, " \
        " %8, %9, %10, %11, %12, %13, %14, %15, " \
        " %16, %17, %18, %19, %20, %21, %22, %23, " \
        " %24, %25, %26, %27, %28, %29, %30, %31}, [%32];" \
        : "=r"((r)[0]),  "=r"((r)[1]),  "=r"((r)[2]),  "=r"((r)[3]), \
          "=r"((r)[4]),  "=r"((r)[5]),  "=r"((r)[6]),  "=r"((r)[7]), \
          "=r"((r)[8]),  "=r"((r)[9]),  "=r"((r)[10]), "=r"((r)[11]), \
          "=r"((r)[12]), "=r"((r)[13]), "=r"((r)[14]), "=r"((r)[15]), \
          "=r"((r)[16]), "=r"((r)[17]), "=r"((r)[18]), "=r"((r)[19]), \
          "=r"((r)[20]), "=r"((r)[21]), "=r"((r)[22]), "=r"((r)[23]), \
          "=r"((r)[24]), "=r"((r)[25]), "=r"((r)[26]), "=r"((r)[27]), \
          "=r"((r)[28]), "=r"((r)[29]), "=r"((r)[30]), "=r"((r)[31]) \
        : "r"(addr))
#endif  // HAS_TCGEN05

// ---------------- convert kernels ----------------
__global__ void cvt_XW(const float* __restrict__ X, const float* __restrict__ W) {
    const size_t NX = (size_t)PIVOT * CHANNELS / 4;
    const size_t NW = (size_t)CHANNELS * CHANNELS / 4;
    size_t i = (size_t)blockIdx.x * blockDim.x + threadIdx.x;
    if (i < NX) {
        float4 f = reinterpret_cast<const float4*>(X)[i];
        __half2* o = reinterpret_cast<__half2*>(Xh_g) + i * 2;
        o[0] = __floats2half2_rn(f.x, f.y);
        o[1] = __floats2half2_rn(f.z, f.w);
    } else if (i < NX + NW) {
        size_t j = i - NX;
        float4 f = reinterpret_cast<const float4*>(W)[j];
        __half2* o = reinterpret_cast<__half2*>(Wh_g) + j * 2;
        o[0] = __floats2half2_rn(f.x, f.y);
        o[1] = __floats2half2_rn(f.z, f.w);
    }
}
// Deinterleave J: A2[2p+k][j] = J[p][2j+k]
__global__ void cvt_J(const float* __restrict__ J) {
    size_t i = (size_t)blockIdx.x * blockDim.x + threadIdx.x;  // float4 index
    size_t p = i >> 9, q = i & 511;
    float4 f = reinterpret_cast<const float4*>(J)[i];
    reinterpret_cast<__half2*>(A2_g + (2 * p) * CHANNELS)[q]     = __floats2half2_rn(f.x, f.z);
    reinterpret_cast<__half2*>(A2_g + (2 * p + 1) * CHANNELS)[q] = __floats2half2_rn(f.y, f.w);
}

// ---------------- cluster-4 multicast TMA tcgen05 GEMM: 256x256x64 ----------------
// Cluster = 2 m-tiles x 2 n-tiles. A shared by the n-pair {r, r^1},
// B (W) shared by the m-pair {r, r^2}; each CTA loads a 128-row half and
// multicasts it. Per-CTA fetched bytes per tile: 32 KB (was 64 KB).
#define BM 256
#define BN 256
#define BK 64
#define ST 3
#define KT (CHANNELS / BK)                   // 16
#define STAGE_B 65536                        // A 32KB + B 32KB (delivered)
#define HALF_B 16384                         // one 128-row slice
#define STAGES0 4096
#define SMEM_TOTAL (STAGES0 + ST * STAGE_B)  // 200704
// idesc: f32 acc (1<<4), f16 a/b, N=256 -> (N/8)<<17, M=128 -> (M/16)<<24
#define IDESC ((1u << 4) | (32u << 17) | (8u << 24))
// ctrl smem: [0,4) tmem ptr; full[s] @ 16+8s (cnt 1, tx 64KB); done[s] @ 48+8s (cnt 3); fin @ 80

template<int EPI>
__global__ void __launch_bounds__(256, 1) __cluster_dims__(4, 1, 1)
gemm_mc(const __grid_constant__ CUtensorMap mapA,
        const __grid_constant__ CUtensorMap mapB,
        const __half* __restrict__ Araw, const __half* __restrict__ Wraw,
        const float* __restrict__ aux,   // EPI0: bias; EPI1: h = out[0:PIVOT]
        float* __restrict__ outp)        // EPI0: out;  EPI1: out2
{
#if HAS_TCGEN05
    extern __shared__ char smem[];
    const uint32_t sbase = smem_u32(smem);
    const int tid = threadIdx.x, wid = tid >> 5, lane = tid & 31;
    const uint32_t rank = ctarank();
    const int m0 = (blockIdx.y * 2 + (int)(rank >> 1)) * BM;
    const int n0 = ((int)(blockIdx.x >> 2) * 2 + (int)(rank & 1)) * BN;
    const uint16_t maskA = (uint16_t)(0x3u << (rank & 2));   // n-pair sharing A
    const uint16_t maskB = (uint16_t)(0x5u << (rank & 1));   // m-pair sharing B
    const uint16_t maskD = (uint16_t)(0xFu & ~(1u << (rank ^ 3u)));  // self + both peers

    if (wid == 7) { TCG_ALLOC(sbase, 512); TCG_RELINQ(); }
    if (tid == 0) {
        #pragma unroll
        for (int s = 0; s < ST; s++) { MBAR_INIT(sbase + 16 + 8 * s, 1); MBAR_INIT(sbase + 48 + 8 * s, 3); }
        MBAR_INIT(sbase + 80, 1);
    }
    __syncthreads();
    uint32_t tmem;
    asm volatile("ld.shared.b32 %0, [%1];" : "=r"(tmem) : "r"(sbase));
    CLUSTER_SYNC();   // all cluster barriers initialized before any multicast TMA

    if (wid == 6) {
        // -------- TMA producer warp: 2 multicast half-tile ops per tile --------
        auto issue = [&](int kt) {
            const int s = kt % ST;
            const uint32_t stg = sbase + STAGES0 + s * STAGE_B;
            const uint32_t fb  = sbase + 16 + 8 * s;
            const int k0 = kt * BK;
            if (lane == 0) {
                MBAR_EXPECT_TX(fb, STAGE_B);   // 64 KB total from self + peers
                // A half: rows m0 + 128*(rank&1), delivered to n-pair
                tma2d_mc(stg + HALF_B * (rank & 1), &mapA,
                         k0, m0 + 128 * (int)(rank & 1), fb, maskA);
                // B half: rows n0 + 128*((rank>>1)&1), delivered to m-pair
                tma2d_mc(stg + 32768 + HALF_B * ((rank >> 1) & 1), &mapB,
                         k0, n0 + 128 * (int)((rank >> 1) & 1), fb, maskB);
            }
        };
        issue(0); issue(1); issue(2);
        #pragma unroll 1
        for (int kt = 0; kt + 3 < KT; kt++) {
            mbar_wait(sbase + 48 + 8 * (kt % ST), (uint32_t)((kt / ST) & 1));
            issue(kt + 3);
        }
    } else if (wid == 7) {
        // -------- MMA consumer warp --------
        #pragma unroll 1
        for (int kt = 0; kt < KT; kt++) {
            const int s = kt % ST;
            mbar_wait(sbase + 16 + 8 * s, (uint32_t)((kt / ST) & 1));
            if (elect_one()) {
                const uint32_t stg = sbase + STAGES0 + s * STAGE_B;
                uint64_t ad = make_desc(stg);
                uint64_t bd = make_desc(stg + 32768);
                #pragma unroll
                for (int ks = 0; ks < 4; ks++) {
                    uint32_t en = (kt > 0 || ks > 0) ? 1u : 0u;
                    mma_f16_ss(tmem,       ad + 2 * ks,        bd + 2 * ks, IDESC, en);
                    mma_f16_ss(tmem + 256, ad + 1024 + 2 * ks, bd + 2 * ks, IDESC, en);
                }
                if (kt < KT - 1) TCG_COMMIT_MC(sbase + 48 + 8 * s, maskD);
                else             TCG_COMMIT(sbase + 80);
            }
        }
    }

    // -------- all threads: wait for final MMA (sleeping wait) --------
    mbar_wait(sbase + 80, 0);
    TCG_FENCE_AFTER();
    FENCE_ASYNC();
    __syncthreads();

    const int half = wid >> 2, sub = wid & 3;

    if (EPI == 0) {
        float* bs = reinterpret_cast<float*>(smem + 1024);   // 256 floats
        bs[tid] = aux[n0 + tid];
        __syncthreads();
        const int row = m0 + half * 128 + sub * 32 + lane;
        #pragma unroll 1
        for (int cc = 0; cc < 8; cc++) {
            uint32_t d[32];
            TCG_LD_X32(d, tmem + half * 256 + cc * 32);
            TCG_WAIT_LD();
            float* orow = outp + (size_t)row * CHANNELS + n0 + cc * 32;
            #pragma unroll
            for (int j = 0; j < 32; j += 4) {
                float4 o;
                o.x = tanhf(__uint_as_float(d[j + 0]) + bs[cc * 32 + j + 0]);
                o.y = tanhf(__uint_as_float(d[j + 1]) + bs[cc * 32 + j + 1]);
                o.z = tanhf(__uint_as_float(d[j + 2]) + bs[cc * 32 + j + 2]);
                o.w = tanhf(__uint_as_float(d[j + 3]) + bs[cc * 32 + j + 3]);
                *reinterpret_cast<float4*>(orow + j) = o;
            }
        }
    } else {
        // stage h tile: 128 p-rows x 256 cols, stride 260 floats (in stage area)
        float* hs = reinterpret_cast<float*>(smem + STAGES0);
        const int p0 = m0 >> 1;
        #pragma unroll
        for (int it = 0; it < 32; it++) {
            int idx = tid + it * 256;                 // 8192 float4
            int pr = idx >> 6, c4 = (idx & 63) * 4;
            float4 v = *reinterpret_cast<const float4*>(
                aux + (size_t)(p0 + pr) * CHANNELS + n0 + c4);
            *reinterpret_cast<float4*>(hs + pr * 260 + c4) = v;
        }
        __syncthreads();
        const int v = half * 128 + sub * 32 + lane;   // virtual row in tile
        const int pl = v >> 1;
        const float* hrow = hs + pl * 260;
        float* obase = outp + (size_t)(p0 + pl) * 2048 + 2 * (size_t)n0;
        #pragma unroll 1
        for (int cc = 0; cc < 8; cc++) {
            uint32_t d[32];
            TCG_LD_X32(d, tmem + half * 256 + cc * 32);
            TCG_WAIT_LD();
            #pragma unroll
            for (int j = 0; j < 32; j++) {
                int cl = cc * 32 + j;
                float hv = hrow[cl];
                float r = (1.f - hv * hv) * __uint_as_float(d[j]);
                float other = __shfl_xor_sync(0xFFFFFFFFu, r, 1);
                if ((lane & 1) == 0)
                    *reinterpret_cast<float2*>(obase + 2 * cl) = make_float2(r, other);
            }
        }
    }

    TCG_FENCE_BEFORE();
    __syncthreads();
    CLUSTER_SYNC();   // all peer commits/TMA into my smem have landed
    if (tid == 0) {
        #pragma unroll
        for (int s = 0; s < ST; s++) { MBAR_INVAL(sbase + 16 + 8 * s); MBAR_INVAL(sbase + 48 + 8 * s); }
        MBAR_INVAL(sbase + 80);
    }
    __syncthreads();
    if (wid == 7) TCG_DEALLOC(tmem, 512);
    CLUSTER_SYNC();

#else  // ---------- non-sm_103a fallback (never runs on GB300) ----------
    const int tid = threadIdx.x;
    const int rank = (int)(blockIdx.x & 3);
    const int m0 = (blockIdx.y * 2 + (rank >> 1)) * BM;
    const int n0 = ((int)(blockIdx.x >> 2) * 2 + (rank & 1)) * BN;
    for (int idx = tid; idx < BM * BN; idx += blockDim.x) {
        int mi = idx >> 8, ni = idx & 255;
        int m = m0 + mi, n = n0 + ni;
        float acc = 0.f;
        for (int k = 0; k < CHANNELS; k++)
            acc += __half2float(Araw[(size_t)m * CHANNELS + k]) *
                   __half2float(Wraw[(size_t)n * CHANNELS + k]);
        if (EPI == 0) {
            outp[(size_t)m * CHANNELS + n] = tanhf(acc + aux[n]);
        } else {
            int p = m >> 1, kb = m & 1;
            float hv = aux[(size_t)p * CHANNELS + n];
            outp[(size_t)p * 2048 + 2 * (size_t)n + kb] = (1.f - hv * hv) * acc;
        }
    }
#endif
}

// ---------------- host launcher ----------------
typedef CUresult (*tmap_encode_fn)(
    CUtensorMap*, CUtensorMapDataType, cuuint32_t, void*,
    const cuuint64_t*, const cuuint64_t*, const cuuint32_t*, const cuuint32_t*,
    CUtensorMapInterleave, CUtensorMapSwizzle, CUtensorMapL2promotion,
    CUtensorMapFloatOOBfill);

static void make_map2d(tmap_encode_fn enc, CUtensorMap* m, void* base, unsigned long long rows) {
    cuuint64_t dims[2]    = {(cuuint64_t)CHANNELS, (cuuint64_t)rows};
    cuuint64_t strides[1] = {(cuuint64_t)(CHANNELS * sizeof(__half))};
    cuuint32_t box[2]     = {64u, 128u};   // 128-row half-tile slices
    cuuint32_t es[2]      = {1u, 1u};
    enc(m, CU_TENSOR_MAP_DATA_TYPE_FLOAT16, 2, base, dims, strides, box, es,
        CU_TENSOR_MAP_INTERLEAVE_NONE, CU_TENSOR_MAP_SWIZZLE_128B,
        CU_TENSOR_MAP_L2_PROMOTION_L2_128B, CU_TENSOR_MAP_FLOAT_OOB_FILL_NONE);
}

extern "C" void kernel_launch(void* const* d_in, const int* in_sizes, int n_in,
                              void* d_out, int out_size)
{
    const float* x = (const float*)d_in[0];   // [3*PIVOT, CHANNELS]
    const float* W = (const float*)d_in[1];   // [CHANNELS, CHANNELS]
    const float* b = (const float*)d_in[2];   // [CHANNELS]
    float* out = (float*)d_out;

    void *pX = nullptr, *pW = nullptr, *pA2 = nullptr;
    cudaGetSymbolAddress(&pX,  Xh_g);
    cudaGetSymbolAddress(&pW,  Wh_g);
    cudaGetSymbolAddress(&pA2, A2_g);

    void* encp = nullptr;
    cudaDriverEntryPointQueryResult qr;
    cudaGetDriverEntryPoint("cuTensorMapEncodeTiled", &encp, cudaEnableDefault, &qr);
    tmap_encode_fn enc = (tmap_encode_fn)encp;

    CUtensorMap mX, mW, mA2;
    make_map2d(enc, &mX,  pX,  PIVOT);
    make_map2d(enc, &mW,  pW,  CHANNELS);
    make_map2d(enc, &mA2, pA2, 2 * PIVOT);

    cudaFuncSetAttribute(gemm_mc<0>, cudaFuncAttributeMaxDynamicSharedMemorySize, SMEM_TOTAL);
    cudaFuncSetAttribute(gemm_mc<1>, cudaFuncAttributeMaxDynamicSharedMemorySize, SMEM_TOTAL);

    const size_t NX = (size_t)PIVOT * CHANNELS / 4;
    const size_t NW = (size_t)CHANNELS * CHANNELS / 4;
    cvt_XW<<<(unsigned)((NX + NW) / 256), 256>>>(x, W);
    cvt_J<<<(unsigned)((size_t)PIVOT * 512 / 256), 256>>>(x + (size_t)PIVOT * CHANNELS);

    // k1: clusters of 4 span blockIdx.x; x = 8 (2 n-pairs), y = 32 (m-pairs)
    dim3 g1(8, PIVOT / (2 * BM));                // (8, 32) = 256 CTAs
    gemm_mc<0><<<g1, 256, SMEM_TOTAL>>>(mX, mW, (const __half*)pX, (const __half*)pW, b, out);

    dim3 g2(8, (2 * PIVOT) / (2 * BM));          // (8, 64) = 512 CTAs
    gemm_mc<1><<<g2, 256, SMEM_TOTAL>>>(mA2, mW, (const __half*)pA2, (const __half*)pW,
                                        out, out + (size_t)PIVOT * CHANNELS);
}

// round 12
// speedup vs baseline: 1.0275x; 1.0275x over previous
#include <cuda_runtime.h>
#include <cuda_fp16.h>
#include <cuda.h>
#include <cstdint>
#include <cstddef>

#define CHANNELS 1024
#define PIVOT 16384

// tcgen05/TMA are arch-SPECIFIC. The harness also compiles a non-'a'
// compute_103 PTX pass; give it a plain-CUDA fallback body.
#if defined(__CUDA_ARCH_FEAT_SM103_ALL) || defined(__CUDA_ARCH_FEAT_SM100_ALL) || defined(__CUDA_ARCH_SPECIFIC__)
#define HAS_TCGEN05 1
#else
#define HAS_TCGEN05 0
#endif

// ---------------- scratch (static device arrays are allowed) ----------
__device__ __align__(1024) __half Xh_g[(size_t)PIVOT * CHANNELS];        // 32 MB
__device__ __align__(1024) __half Wh_g[(size_t)CHANNELS * CHANNELS];     //  2 MB
__device__ __align__(1024) __half A2_g[(size_t)2 * PIVOT * CHANNELS];    // 64 MB

// ---------------- device helpers ----------------
__device__ __forceinline__ uint32_t smem_u32(const void* p) {
    uint32_t r;
    asm("{ .reg .u64 t; cvta.to.shared.u64 t, %1; cvt.u32.u64 %0, t; }" : "=r"(r) : "l"(p));
    return r;
}
__device__ __forceinline__ uint32_t elect_one() {
    uint32_t p;
    asm volatile("{ .reg .pred p; elect.sync _|p, 0xFFFFFFFF; selp.b32 %0, 1, 0, p; }" : "=r"(p));
    return p;
}
// SW64 K-major smem descriptor (layout=4, version=1, SBO=32, LBO=1)
// SW64 atom = 8 rows x 64 B; rows here are 64 B (BK=32 f16).
__device__ __forceinline__ uint64_t make_desc64(uint32_t addr) {
    const uint64_t base = (uint64_t(4) << 61) | (uint64_t(1) << 46)
                        | (uint64_t(32) << 32) | (uint64_t(1) << 16);
    return base | ((uint64_t)(addr >> 4) & 0x3FFF);
}

#if HAS_TCGEN05
#define TCG_ALLOC(smem_res, ncols) \
    asm volatile("tcgen05.alloc.cta_group::1.sync.aligned.shared::cta.b32 [%0], %1;" \
                 :: "r"(smem_res), "r"((uint32_t)(ncols)) : "memory")
#define TCG_RELINQ() \
    asm volatile("tcgen05.relinquish_alloc_permit.cta_group::1.sync.aligned;")
#define TCG_DEALLOC(tmem, ncols) \
    asm volatile("tcgen05.dealloc.cta_group::1.sync.aligned.b32 %0, %1;" \
                 :: "r"(tmem), "r"((uint32_t)(ncols)))
#define TCG_COMMIT(mbar) \
    asm volatile("tcgen05.commit.cta_group::1.mbarrier::arrive::one.shared::cluster.b64 [%0];" \
                 :: "r"(mbar) : "memory")
#define TCG_FENCE_AFTER()  asm volatile("tcgen05.fence::after_thread_sync;" ::: "memory")
#define TCG_FENCE_BEFORE() asm volatile("tcgen05.fence::before_thread_sync;" ::: "memory")
#define TCG_WAIT_LD()      asm volatile("tcgen05.wait::ld.sync.aligned;" ::: "memory")
#define FENCE_ASYNC()      asm volatile("fence.proxy.async.shared::cta;" ::: "memory")
#define MBAR_INIT(addr, cnt) \
    asm volatile("mbarrier.init.shared.b64 [%0], %1;" :: "r"(addr), "r"((uint32_t)(cnt)) : "memory")
#define MBAR_INVAL(addr) \
    asm volatile("mbarrier.inval.shared.b64 [%0];" :: "r"(addr) : "memory")
#define MBAR_EXPECT_TX(addr, bytes) \
    asm volatile("mbarrier.arrive.expect_tx.shared.b64 _, [%0], %1;" \
                 :: "r"(addr), "r"((uint32_t)(bytes)) : "memory")

// Sleep-hint wait (HW TRYWAIT, no hot poll)
__device__ __forceinline__ void mbar_wait(uint32_t addr, uint32_t parity) {
    asm volatile(
        "{\n\t.reg .pred P;\n\t"
        "W_%=:\n\t"
        "mbarrier.try_wait.parity.shared.b64 P, [%0], %1, 0x989680;\n\t"
        "@!P bra W_%=;\n\t}"
        :: "r"(addr), "r"(parity) : "memory");
}
__device__ __forceinline__ void tma2d(uint32_t dst, const void* map,
                                      int32_t cx, int32_t cy, uint32_t mbar) {
    asm volatile(
        "cp.async.bulk.tensor.2d.shared::cta.global.tile.mbarrier::complete_tx::bytes "
        "[%0], [%1, {%2, %3}], [%4];"
        :: "r"(dst), "l"(map), "r"(cx), "r"(cy), "r"(mbar) : "memory");
}
__device__ __forceinline__ void mma_f16_ss(uint32_t d_tmem, uint64_t a_desc,
                                           uint64_t b_desc, uint32_t idesc, uint32_t en) {
    asm volatile(
        "{\n\t.reg .pred p;\n\t"
        "setp.ne.u32 p, %4, 0;\n\t"
        "tcgen05.mma.cta_group::1.kind::f16 [%0], %1, %2, %3, {%5,%5,%5,%5}, p;\n\t}"
        :: "r"(d_tmem), "l"(a_desc), "l"(b_desc), "r"(idesc), "r"(en), "r"(0u) : "memory");
}
#define TCG_LD_X32(r, addr) \
    asm volatile( \
        "tcgen05.ld.sync.aligned.32x32b.x32.b32 " \
        "{%0, %1, %2, %3, %4, %5, %6, %7, " \
        " %8, %9, %10, %11, %12, %13, %14, %15, " \
        " %16, %17, %18, %19, %20, %21, %22, %23, " \
        " %24, %25, %26, %27, %28, %29, %30, %31}, [%32];" \
        : "=r"((r)[0]),  "=r"((r)[1]),  "=r"((r)[2]),  "=r"((r)[3]), \
          "=r"((r)[4]),  "=r"((r)[5]),  "=r"((r)[6]),  "=r"((r)[7]), \
          "=r"((r)[8]),  "=r"((r)[9]),  "=r"((r)[10]), "=r"((r)[11]), \
          "=r"((r)[12]), "=r"((r)[13]), "=r"((r)[14]), "=r"((r)[15]), \
          "=r"((r)[16]), "=r"((r)[17]), "=r"((r)[18]), "=r"((r)[19]), \
          "=r"((r)[20]), "=r"((r)[21]), "=r"((r)[22]), "=r"((r)[23]), \
          "=r"((r)[24]), "=r"((r)[25]), "=r"((r)[26]), "=r"((r)[27]), \
          "=r"((r)[28]), "=r"((r)[29]), "=r"((r)[30]), "=r"((r)[31]) \
        : "r"(addr))
#endif  // HAS_TCGEN05

// ---------------- convert kernels ----------------
__global__ void cvt_XW(const float* __restrict__ X, const float* __restrict__ W) {
    const size_t NX = (size_t)PIVOT * CHANNELS / 4;
    const size_t NW = (size_t)CHANNELS * CHANNELS / 4;
    size_t i = (size_t)blockIdx.x * blockDim.x + threadIdx.x;
    if (i < NX) {
        float4 f = reinterpret_cast<const float4*>(X)[i];
        __half2* o = reinterpret_cast<__half2*>(Xh_g) + i * 2;
        o[0] = __floats2half2_rn(f.x, f.y);
        o[1] = __floats2half2_rn(f.z, f.w);
    } else if (i < NX + NW) {
        size_t j = i - NX;
        float4 f = reinterpret_cast<const float4*>(W)[j];
        __half2* o = reinterpret_cast<__half2*>(Wh_g) + j * 2;
        o[0] = __floats2half2_rn(f.x, f.y);
        o[1] = __floats2half2_rn(f.z, f.w);
    }
}
// Deinterleave J: A2[2p+k][j] = J[p][2j+k]
__global__ void cvt_J(const float* __restrict__ J) {
    size_t i = (size_t)blockIdx.x * blockDim.x + threadIdx.x;  // float4 index
    size_t p = i >> 9, q = i & 511;
    float4 f = reinterpret_cast<const float4*>(J)[i];
    reinterpret_cast<__half2*>(A2_g + (2 * p) * CHANNELS)[q]     = __floats2half2_rn(f.x, f.z);
    reinterpret_cast<__half2*>(A2_g + (2 * p + 1) * CHANNELS)[q] = __floats2half2_rn(f.y, f.w);
}

// ---------------- deep-pipeline TMA tcgen05 GEMM: 256x256x32, 6 stages ----------------
// Same 256x256 tile (traffic-optimal) but BK=32 / SW64 so the stage shrinks to
// 32 KB and the pipeline deepens to 6 stages: P = (T_mma + T_tma)/ST.
#define BM 256
#define BN 256
#define BK 32
#define ST 6
#define KT (CHANNELS / BK)                   // 32
#define STAGE_B 32768                        // A 16KB + B 16KB
#define STAGES0 4096
#define SMEM_TOTAL (STAGES0 + ST * STAGE_B)  // 200704
// idesc: f32 acc (1<<4), f16 a/b, N=256 -> (N/8)<<17, M=128 -> (M/16)<<24
#define IDESC ((1u << 4) | (32u << 17) | (8u << 24))
// ctrl smem: [0,4) tmem ptr; full[s] @ 16+8s; done[s] @ 64+8s; fin @ 120; bias @ 1024
// warp roles: 7 = MMA consumer, 6 = TMA producer, 0-5 parked on sleeping fin wait

template<int EPI>
__global__ void __launch_bounds__(256, 1) gemm_tma(
    const __grid_constant__ CUtensorMap mapA,
    const __grid_constant__ CUtensorMap mapB,
    const __half* __restrict__ Araw, const __half* __restrict__ Wraw,
    const float* __restrict__ aux,   // EPI0: bias; EPI1: h = out[0:PIVOT]
    float* __restrict__ outp)        // EPI0: out;  EPI1: out2
{
#if HAS_TCGEN05
    extern __shared__ char smem[];
    const uint32_t sbase = smem_u32(smem);
    const int tid = threadIdx.x, wid = tid >> 5, lane = tid & 31;
    const int m0 = blockIdx.y * BM, n0 = blockIdx.x * BN;

    if (wid == 7) { TCG_ALLOC(sbase, 512); TCG_RELINQ(); }
    if (tid == 0) {
        #pragma unroll
        for (int s = 0; s < ST; s++) { MBAR_INIT(sbase + 16 + 8 * s, 1); MBAR_INIT(sbase + 64 + 8 * s, 1); }
        MBAR_INIT(sbase + 120, 1);
    }
    __syncthreads();
    uint32_t tmem;
    asm volatile("ld.shared.b32 %0, [%1];" : "=r"(tmem) : "r"(sbase));

    if (wid == 6) {
        // -------- TMA producer warp --------
        auto issue = [&](int kt) {
            const int s = kt % ST;
            const uint32_t stg = sbase + STAGES0 + s * STAGE_B;
            const uint32_t fb  = sbase + 16 + 8 * s;
            if (lane == 0) {
                MBAR_EXPECT_TX(fb, STAGE_B);
                tma2d(stg,         &mapA, kt * BK, m0, fb);
                tma2d(stg + 16384, &mapB, kt * BK, n0, fb);
            }
        };
        #pragma unroll
        for (int k = 0; k < ST; k++) issue(k);
        #pragma unroll 1
        for (int kt = 0; kt + ST < KT; kt++) {
            mbar_wait(sbase + 64 + 8 * (kt % ST), (uint32_t)((kt / ST) & 1));
            issue(kt + ST);
        }
    } else if (wid == 7) {
        // -------- MMA consumer warp --------
        #pragma unroll 1
        for (int kt = 0; kt < KT; kt++) {
            const int s = kt % ST;
            mbar_wait(sbase + 16 + 8 * s, (uint32_t)((kt / ST) & 1));
            if (elect_one()) {
                const uint32_t stg = sbase + STAGES0 + s * STAGE_B;
                uint64_t ad = make_desc64(stg);
                uint64_t bd = make_desc64(stg + 16384);
                #pragma unroll
                for (int ks = 0; ks < 2; ks++) {        // 2 x K16 per k-tile
                    uint32_t en = (kt > 0 || ks > 0) ? 1u : 0u;
                    mma_f16_ss(tmem,       ad + 2 * ks,       bd + 2 * ks, IDESC, en);
                    mma_f16_ss(tmem + 256, ad + 512 + 2 * ks, bd + 2 * ks, IDESC, en);
                }
                TCG_COMMIT((kt < KT - 1) ? (sbase + 64 + 8 * s) : (sbase + 120));
            }
        }
    }

    // -------- all threads: wait for final MMA (sleeping wait) --------
    mbar_wait(sbase + 120, 0);
    TCG_FENCE_AFTER();
    FENCE_ASYNC();
    __syncthreads();

    const int half = wid >> 2, sub = wid & 3;

    if (EPI == 0) {
        float* bs = reinterpret_cast<float*>(smem + 1024);   // 256 floats
        bs[tid] = aux[n0 + tid];
        __syncthreads();
        const int row = m0 + half * 128 + sub * 32 + lane;
        #pragma unroll 1
        for (int cc = 0; cc < 8; cc++) {
            uint32_t d[32];
            TCG_LD_X32(d, tmem + half * 256 + cc * 32);
            TCG_WAIT_LD();
            float* orow = outp + (size_t)row * CHANNELS + n0 + cc * 32;
            #pragma unroll
            for (int j = 0; j < 32; j += 4) {
                float4 o;
                o.x = tanhf(__uint_as_float(d[j + 0]) + bs[cc * 32 + j + 0]);
                o.y = tanhf(__uint_as_float(d[j + 1]) + bs[cc * 32 + j + 1]);
                o.z = tanhf(__uint_as_float(d[j + 2]) + bs[cc * 32 + j + 2]);
                o.w = tanhf(__uint_as_float(d[j + 3]) + bs[cc * 32 + j + 3]);
                *reinterpret_cast<float4*>(orow + j) = o;
            }
        }
    } else {
        // stage h tile: 128 p-rows x 256 cols, stride 260 floats (in stage area)
        float* hs = reinterpret_cast<float*>(smem + STAGES0);
        const int p0 = m0 >> 1;
        #pragma unroll
        for (int it = 0; it < 32; it++) {
            int idx = tid + it * 256;                 // 8192 float4
            int pr = idx >> 6, c4 = (idx & 63) * 4;
            float4 v = *reinterpret_cast<const float4*>(
                aux + (size_t)(p0 + pr) * CHANNELS + n0 + c4);
            *reinterpret_cast<float4*>(hs + pr * 260 + c4) = v;
        }
        __syncthreads();
        const int v = half * 128 + sub * 32 + lane;   // virtual row in tile
        const int pl = v >> 1;
        const float* hrow = hs + pl * 260;
        float* obase = outp + (size_t)(p0 + pl) * 2048 + 2 * (size_t)n0;
        #pragma unroll 1
        for (int cc = 0; cc < 8; cc++) {
            uint32_t d[32];
            TCG_LD_X32(d, tmem + half * 256 + cc * 32);
            TCG_WAIT_LD();
            #pragma unroll
            for (int j = 0; j < 32; j++) {
                int cl = cc * 32 + j;
                float hv = hrow[cl];
                float r = (1.f - hv * hv) * __uint_as_float(d[j]);
                float other = __shfl_xor_sync(0xFFFFFFFFu, r, 1);
                if ((lane & 1) == 0)
                    *reinterpret_cast<float2*>(obase + 2 * cl) = make_float2(r, other);
            }
        }
    }

    TCG_FENCE_BEFORE();
    __syncthreads();
    if (tid == 0) {
        #pragma unroll
        for (int s = 0; s < ST; s++) { MBAR_INVAL(sbase + 16 + 8 * s); MBAR_INVAL(sbase + 64 + 8 * s); }
        MBAR_INVAL(sbase + 120);
    }
    __syncthreads();
    if (wid == 7) TCG_DEALLOC(tmem, 512);

#else  // ---------- non-sm_103a fallback (never runs on GB300) ----------
    const int tid = threadIdx.x;
    const int m0 = blockIdx.y * BM, n0 = blockIdx.x * BN;
    for (int idx = tid; idx < BM * BN; idx += blockDim.x) {
        int mi = idx >> 8, ni = idx & 255;
        int m = m0 + mi, n = n0 + ni;
        float acc = 0.f;
        for (int k = 0; k < CHANNELS; k++)
            acc += __half2float(Araw[(size_t)m * CHANNELS + k]) *
                   __half2float(Wraw[(size_t)n * CHANNELS + k]);
        if (EPI == 0) {
            outp[(size_t)m * CHANNELS + n] = tanhf(acc + aux[n]);
        } else {
            int p = m >> 1, kb = m & 1;
            float hv = aux[(size_t)p * CHANNELS + n];
            outp[(size_t)p * 2048 + 2 * (size_t)n + kb] = (1.f - hv * hv) * acc;
        }
    }
#endif
}

// ---------------- host launcher ----------------
typedef CUresult (*tmap_encode_fn)(
    CUtensorMap*, CUtensorMapDataType, cuuint32_t, void*,
    const cuuint64_t*, const cuuint64_t*, const cuuint32_t*, const cuuint32_t*,
    CUtensorMapInterleave, CUtensorMapSwizzle, CUtensorMapL2promotion,
    CUtensorMapFloatOOBfill);

static void make_map2d(tmap_encode_fn enc, CUtensorMap* m, void* base, unsigned long long rows) {
    cuuint64_t dims[2]    = {(cuuint64_t)CHANNELS, (cuuint64_t)rows};
    cuuint64_t strides[1] = {(cuuint64_t)(CHANNELS * sizeof(__half))};
    cuuint32_t box[2]     = {32u, 256u};     // 32 f16 = 64 B rows -> SW64
    cuuint32_t es[2]      = {1u, 1u};
    enc(m, CU_TENSOR_MAP_DATA_TYPE_FLOAT16, 2, base, dims, strides, box, es,
        CU_TENSOR_MAP_INTERLEAVE_NONE, CU_TENSOR_MAP_SWIZZLE_64B,
        CU_TENSOR_MAP_L2_PROMOTION_L2_128B, CU_TENSOR_MAP_FLOAT_OOB_FILL_NONE);
}

extern "C" void kernel_launch(void* const* d_in, const int* in_sizes, int n_in,
                              void* d_out, int out_size)
{
    const float* x = (const float*)d_in[0];   // [3*PIVOT, CHANNELS]
    const float* W = (const float*)d_in[1];   // [CHANNELS, CHANNELS]
    const float* b = (const float*)d_in[2];   // [CHANNELS]
    float* out = (float*)d_out;

    void *pX = nullptr, *pW = nullptr, *pA2 = nullptr;
    cudaGetSymbolAddress(&pX,  Xh_g);
    cudaGetSymbolAddress(&pW,  Wh_g);
    cudaGetSymbolAddress(&pA2, A2_g);

    void* encp = nullptr;
    cudaDriverEntryPointQueryResult qr;
    cudaGetDriverEntryPoint("cuTensorMapEncodeTiled", &encp, cudaEnableDefault, &qr);
    tmap_encode_fn enc = (tmap_encode_fn)encp;

    CUtensorMap mX, mW, mA2;
    make_map2d(enc, &mX,  pX,  PIVOT);
    make_map2d(enc, &mW,  pW,  CHANNELS);
    make_map2d(enc, &mA2, pA2, 2 * PIVOT);

    cudaFuncSetAttribute(gemm_tma<0>, cudaFuncAttributeMaxDynamicSharedMemorySize, SMEM_TOTAL);
    cudaFuncSetAttribute(gemm_tma<1>, cudaFuncAttributeMaxDynamicSharedMemorySize, SMEM_TOTAL);

    const size_t NX = (size_t)PIVOT * CHANNELS / 4;
    const size_t NW = (size_t)CHANNELS * CHANNELS / 4;
    cvt_XW<<<(unsigned)((NX + NW) / 256), 256>>>(x, W);
    cvt_J<<<(unsigned)((size_t)PIVOT * 512 / 256), 256>>>(x + (size_t)PIVOT * CHANNELS);

    dim3 g1(CHANNELS / BN, PIVOT / BM);          // (4, 64)
    gemm_tma<0><<<g1, 256, SMEM_TOTAL>>>(mX, mW, (const __half*)pX, (const __half*)pW, b, out);

    dim3 g2(CHANNELS / BN, (2 * PIVOT) / BM);    // (4, 128)
    gemm_tma<1><<<g2, 256, SMEM_TOTAL>>>(mA2, mW, (const __half*)pA2, (const __half*)pW,
                                         out, out + (size_t)PIVOT * CHANNELS);
}

// round 14
// speedup vs baseline: 1.2655x; 1.2316x over previous
#include <cuda_runtime.h>
#include <cuda_fp16.h>
#include <cuda.h>
#include <cstdint>
#include <cstddef>

#define CHANNELS 1024
#define PIVOT 16384

// tcgen05/TMA are arch-SPECIFIC. The harness also compiles a non-'a'
// compute_103 PTX pass; give it a plain-CUDA fallback body.
#if defined(__CUDA_ARCH_FEAT_SM103_ALL) || defined(__CUDA_ARCH_FEAT_SM100_ALL) || defined(__CUDA_ARCH_SPECIFIC__)
#define HAS_TCGEN05 1
#else
#define HAS_TCGEN05 0
#endif

// ---------------- scratch (static device arrays are allowed) ----------
__device__ __align__(1024) __half Xh_g[(size_t)PIVOT * CHANNELS];        // 32 MB
__device__ __align__(1024) __half Wh_g[(size_t)CHANNELS * CHANNELS];     //  2 MB
__device__ __align__(1024) __half A2_g[(size_t)2 * PIVOT * CHANNELS];    // 64 MB

// ---------------- device helpers ----------------
__device__ __forceinline__ uint32_t smem_u32(const void* p) {
    uint32_t r;
    asm("{ .reg .u64 t; cvta.to.shared.u64 t, %1; cvt.u32.u64 %0, t; }" : "=r"(r) : "l"(p));
    return r;
}
__device__ __forceinline__ uint32_t elect_one() {
    uint32_t p;
    asm volatile("{ .reg .pred p; elect.sync _|p, 0xFFFFFFFF; selp.b32 %0, 1, 0, p; }" : "=r"(p));
    return p;
}
// SW128 K-major smem descriptor (layout=2, version=1, SBO=64, LBO=1)
__device__ __forceinline__ uint64_t make_desc(uint32_t addr) {
    const uint64_t base = (uint64_t(2) << 61) | (uint64_t(1) << 46)
                        | (uint64_t(64) << 32) | (uint64_t(1) << 16);
    return base | ((uint64_t)(addr >> 4) & 0x3FFF);
}

#if HAS_TCGEN05
#define TCG_ALLOC(smem_res, ncols) \
    asm volatile("tcgen05.alloc.cta_group::1.sync.aligned.shared::cta.b32 [%0], %1;" \
                 :: "r"(smem_res), "r"((uint32_t)(ncols)) : "memory")
#define TCG_RELINQ() \
    asm volatile("tcgen05.relinquish_alloc_permit.cta_group::1.sync.aligned;")
#define TCG_DEALLOC(tmem, ncols) \
    asm volatile("tcgen05.dealloc.cta_group::1.sync.aligned.b32 %0, %1;" \
                 :: "r"(tmem), "r"((uint32_t)(ncols)))
#define TCG_COMMIT(mbar) \
    asm volatile("tcgen05.commit.cta_group::1.mbarrier::arrive::one.shared::cluster.b64 [%0];" \
                 :: "r"(mbar) : "memory")
#define TCG_FENCE_AFTER()  asm volatile("tcgen05.fence::after_thread_sync;" ::: "memory")
#define TCG_FENCE_BEFORE() asm volatile("tcgen05.fence::before_thread_sync;" ::: "memory")
#define TCG_WAIT_LD()      asm volatile("tcgen05.wait::ld.sync.aligned;" ::: "memory")
#define FENCE_ASYNC()      asm volatile("fence.proxy.async.shared::cta;" ::: "memory")
#define MBAR_INIT(addr, cnt) \
    asm volatile("mbarrier.init.shared.b64 [%0], %1;" :: "r"(addr), "r"((uint32_t)(cnt)) : "memory")
#define MBAR_INVAL(addr) \
    asm volatile("mbarrier.inval.shared.b64 [%0];" :: "r"(addr) : "memory")
#define MBAR_EXPECT_TX(addr, bytes) \
    asm volatile("mbarrier.arrive.expect_tx.shared.b64 _, [%0], %1;" \
                 :: "r"(addr), "r"((uint32_t)(bytes)) : "memory")

// Sleep-hint wait (HW TRYWAIT, no hot poll)
__device__ __forceinline__ void mbar_wait(uint32_t addr, uint32_t parity) {
    asm volatile(
        "{\n\t.reg .pred P;\n\t"
        "W_%=:\n\t"
        "mbarrier.try_wait.parity.shared.b64 P, [%0], %1, 0x989680;\n\t"
        "@!P bra W_%=;\n\t}"
        :: "r"(addr), "r"(parity) : "memory");
}
__device__ __forceinline__ void tma2d(uint32_t dst, const void* map,
                                      int32_t cx, int32_t cy, uint32_t mbar) {
    asm volatile(
        "cp.async.bulk.tensor.2d.shared::cta.global.tile.mbarrier::complete_tx::bytes "
        "[%0], [%1, {%2, %3}], [%4];"
        :: "r"(dst), "l"(map), "r"(cx), "r"(cy), "r"(mbar) : "memory");
}
__device__ __forceinline__ void mma_f16_ss(uint32_t d_tmem, uint64_t a_desc,
                                           uint64_t b_desc, uint32_t idesc, uint32_t en) {
    asm volatile(
        "{\n\t.reg .pred p;\n\t"
        "setp.ne.u32 p, %4, 0;\n\t"
        "tcgen05.mma.cta_group::1.kind::f16 [%0], %1, %2, %3, {%5,%5,%5,%5}, p;\n\t}"
        :: "r"(d_tmem), "l"(a_desc), "l"(b_desc), "r"(idesc), "r"(en), "r"(0u) : "memory");
}
#define TCG_LD_X32(r, addr) \
    asm volatile( \
        "tcgen05.ld.sync.aligned.32x32b.x32.b32 " \
        "{%0, %1, %2, %3, %4, %5, %6, %7, " \
        " %8, %9, %10, %11, %12, %13, %14, %15, " \
        " %16, %17, %18, %19, %20, %21, %22, %23, " \
        " %24, %25, %26, %27, %28, %29, %30, %31}, [%32];" \
        : "=r"((r)[0]),  "=r"((r)[1]),  "=r"((r)[2]),  "=r"((r)[3]), \
          "=r"((r)[4]),  "=r"((r)[5]),  "=r"((r)[6]),  "=r"((r)[7]), \
          "=r"((r)[8]),  "=r"((r)[9]),  "=r"((r)[10]), "=r"((r)[11]), \
          "=r"((r)[12]), "=r"((r)[13]), "=r"((r)[14]), "=r"((r)[15]), \
          "=r"((r)[16]), "=r"((r)[17]), "=r"((r)[18]), "=r"((r)[19]), \
          "=r"((r)[20]), "=r"((r)[21]), "=r"((r)[22]), "=r"((r)[23]), \
          "=r"((r)[24]), "=r"((r)[25]), "=r"((r)[26]), "=r"((r)[27]), \
          "=r"((r)[28]), "=r"((r)[29]), "=r"((r)[30]), "=r"((r)[31]) \
        : "r"(addr))
#endif  // HAS_TCGEN05

// ---------------- convert kernels ----------------
__global__ void cvt_XW(const float* __restrict__ X, const float* __restrict__ W) {
    const size_t NX = (size_t)PIVOT * CHANNELS / 4;
    const size_t NW = (size_t)CHANNELS * CHANNELS / 4;
    size_t i = (size_t)blockIdx.x * blockDim.x + threadIdx.x;
    if (i < NX) {
        float4 f = reinterpret_cast<const float4*>(X)[i];
        __half2* o = reinterpret_cast<__half2*>(Xh_g) + i * 2;
        o[0] = __floats2half2_rn(f.x, f.y);
        o[1] = __floats2half2_rn(f.z, f.w);
    } else if (i < NX + NW) {
        size_t j = i - NX;
        float4 f = reinterpret_cast<const float4*>(W)[j];
        __half2* o = reinterpret_cast<__half2*>(Wh_g) + j * 2;
        o[0] = __floats2half2_rn(f.x, f.y);
        o[1] = __floats2half2_rn(f.z, f.w);
    }
}
// Deinterleave J: A2[2p+k][j] = J[p][2j+k]
__global__ void cvt_J(const float* __restrict__ J) {
    size_t i = (size_t)blockIdx.x * blockDim.x + threadIdx.x;  // float4 index
    size_t p = i >> 9, q = i & 511;
    float4 f = reinterpret_cast<const float4*>(J)[i];
    reinterpret_cast<__half2*>(A2_g + (2 * p) * CHANNELS)[q]     = __floats2half2_rn(f.x, f.z);
    reinterpret_cast<__half2*>(A2_g + (2 * p + 1) * CHANNELS)[q] = __floats2half2_rn(f.y, f.w);
}

// ---------------- TMA-fed tcgen05 GEMM: 256x256x64, 3 stages ----------------
#define BM 256
#define BN 256
#define BK 64
#define ST 3
#define KT (CHANNELS / BK)                   // 16
#define STAGE_B 65536                        // A 32KB + B 32KB
#define STAGES0 4096
#define SMEM_TOTAL (STAGES0 + ST * STAGE_B)  // 200704
// idesc: f32 acc (1<<4), f16 a/b, N=256 -> (N/8)<<17, M=128 -> (M/16)<<24
#define IDESC ((1u << 4) | (32u << 17) | (8u << 24))
// ctrl smem: [0,4) tmem ptr; full[s] @ 16+8s; done[s] @ 48+8s; fin @ 80; bias @ 1024
// warp roles: 7 = MMA consumer, 6 = TMA producer, 0-5 parked on sleeping fin wait

template<int EPI>
__global__ void __launch_bounds__(256, 1) gemm_tma(
    const __grid_constant__ CUtensorMap mapA,
    const __grid_constant__ CUtensorMap mapB,
    const __half* __restrict__ Araw, const __half* __restrict__ Wraw,
    const float* __restrict__ aux,   // EPI0: bias; EPI1: h = out[0:PIVOT]
    float* __restrict__ outp)        // EPI0: out;  EPI1: out2
{
#if HAS_TCGEN05
    extern __shared__ char smem[];
    const uint32_t sbase = smem_u32(smem);
    const int tid = threadIdx.x, wid = tid >> 5, lane = tid & 31;
    const int m0 = blockIdx.y * BM, n0 = blockIdx.x * BN;

    if (wid == 7) { TCG_ALLOC(sbase, 512); TCG_RELINQ(); }
    if (tid == 0) {
        #pragma unroll
        for (int s = 0; s < ST; s++) { MBAR_INIT(sbase + 16 + 8 * s, 1); MBAR_INIT(sbase + 48 + 8 * s, 1); }
        MBAR_INIT(sbase + 80, 1);
    }
    __syncthreads();
    uint32_t tmem;
    asm volatile("ld.shared.b32 %0, [%1];" : "=r"(tmem) : "r"(sbase));

    if (wid == 6) {
        // -------- TMA producer warp --------
        auto issue = [&](int kt) {
            const int s = kt % ST;
            const uint32_t stg = sbase + STAGES0 + s * STAGE_B;
            const uint32_t fb  = sbase + 16 + 8 * s;
            if (lane == 0) {
                MBAR_EXPECT_TX(fb, STAGE_B);
                tma2d(stg,         &mapA, kt * BK, m0, fb);
                tma2d(stg + 32768, &mapB, kt * BK, n0, fb);
            }
        };
        issue(0); issue(1); issue(2);
        #pragma unroll 1
        for (int kt = 0; kt + 3 < KT; kt++) {
            mbar_wait(sbase + 48 + 8 * (kt % ST), (uint32_t)((kt / ST) & 1));
            issue(kt + 3);
        }
    } else if (wid == 7) {
        // -------- MMA consumer warp --------
        #pragma unroll 1
        for (int kt = 0; kt < KT; kt++) {
            const int s = kt % ST;
            mbar_wait(sbase + 16 + 8 * s, (uint32_t)((kt / ST) & 1));
            if (elect_one()) {
                const uint32_t stg = sbase + STAGES0 + s * STAGE_B;
                uint64_t ad = make_desc(stg);
                uint64_t bd = make_desc(stg + 32768);
                #pragma unroll
                for (int ks = 0; ks < 4; ks++) {
                    uint32_t en = (kt > 0 || ks > 0) ? 1u : 0u;
                    mma_f16_ss(tmem,       ad + 2 * ks,        bd + 2 * ks, IDESC, en);
                    mma_f16_ss(tmem + 256, ad + 1024 + 2 * ks, bd + 2 * ks, IDESC, en);
                }
                TCG_COMMIT((kt < KT - 1) ? (sbase + 48 + 8 * s) : (sbase + 80));
            }
        }
    }

    // -------- all threads: wait for final MMA (sleeping wait) --------
    mbar_wait(sbase + 80, 0);
    TCG_FENCE_AFTER();
    FENCE_ASYNC();          // generic-proxy smem use below after TMA writes
    __syncthreads();

    const int half = wid >> 2, sub = wid & 3;

    if (EPI == 0) {
        float* bs = reinterpret_cast<float*>(smem + 1024);   // 256 floats
        bs[tid] = aux[n0 + tid];
        __syncthreads();
        const int row = m0 + half * 128 + sub * 32 + lane;
        #pragma unroll 1
        for (int cc = 0; cc < 8; cc++) {
            uint32_t d[32];
            TCG_LD_X32(d, tmem + half * 256 + cc * 32);
            TCG_WAIT_LD();
            float* orow = outp + (size_t)row * CHANNELS + n0 + cc * 32;
            #pragma unroll
            for (int j = 0; j < 32; j += 4) {
                float4 o;
                o.x = tanhf(__uint_as_float(d[j + 0]) + bs[cc * 32 + j + 0]);
                o.y = tanhf(__uint_as_float(d[j + 1]) + bs[cc * 32 + j + 1]);
                o.z = tanhf(__uint_as_float(d[j + 2]) + bs[cc * 32 + j + 2]);
                o.w = tanhf(__uint_as_float(d[j + 3]) + bs[cc * 32 + j + 3]);
                *reinterpret_cast<float4*>(orow + j) = o;
            }
        }
    } else {
        // Transposed coalesced epilogue, TWO PASSES (one per TMEM half;
        // rs holds 128 virtual rows x 257 floats = 131.6 KB in the stage area).
        // out2 row p is contiguous: out2[p][2i+k] = rs[2*pr+k][i] * (1-h[p][i]^2).
        float* rs = reinterpret_cast<float*>(smem + STAGES0);
        const int p0 = m0 >> 1;
        #pragma unroll 1
        for (int hh = 0; hh < 2; hh++) {
            if (half == hh) {
                const int vl = sub * 32 + lane;           // 0..127 local virtual row
                #pragma unroll 1
                for (int cc = 0; cc < 8; cc++) {
                    uint32_t d[32];
                    TCG_LD_X32(d, tmem + hh * 256 + cc * 32);
                    TCG_WAIT_LD();
                    #pragma unroll
                    for (int j = 0; j < 32; j++)
                        rs[vl * 257 + cc * 32 + j] = __uint_as_float(d[j]);
                }
            }
            __syncthreads();
            // all 8 warps store the 64 p-rows of this half, fully coalesced
            const int pb = p0 + hh * 64;
            #pragma unroll 1
            for (int r8 = 0; r8 < 8; r8++) {
                const int pr = wid * 8 + r8;              // 0..63 local p-row
                const float* hrow = aux + (size_t)(pb + pr) * CHANNELS + n0;
                float* orow = outp + (size_t)(pb + pr) * 2048 + 2 * (size_t)n0;
                const float* r0 = rs + (2 * pr) * 257;
                const float* r1 = r0 + 257;
                #pragma unroll
                for (int c = 0; c < 4; c++) {
                    const int i0 = 64 * c + 2 * lane;
                    float2 hv = *reinterpret_cast<const float2*>(hrow + i0);
                    float g0 = 1.f - hv.x * hv.x;
                    float g1 = 1.f - hv.y * hv.y;
                    float4 o;
                    o.x = g0 * r0[i0];
                    o.y = g0 * r1[i0];
                    o.z = g1 * r0[i0 + 1];
                    o.w = g1 * r1[i0 + 1];
                    *reinterpret_cast<float4*>(orow + 4 * (32 * c + lane)) = o;
                }
            }
            __syncthreads();
        }
    }

    TCG_FENCE_BEFORE();
    __syncthreads();
    if (tid == 0) {
        #pragma unroll
        for (int s = 0; s < ST; s++) { MBAR_INVAL(sbase + 16 + 8 * s); MBAR_INVAL(sbase + 48 + 8 * s); }
        MBAR_INVAL(sbase + 80);
    }
    __syncthreads();
    if (wid == 7) TCG_DEALLOC(tmem, 512);

#else  // ---------- non-sm_103a fallback (never runs on GB300) ----------
    const int tid = threadIdx.x;
    const int m0 = blockIdx.y * BM, n0 = blockIdx.x * BN;
    for (int idx = tid; idx < BM * BN; idx += blockDim.x) {
        int mi = idx >> 8, ni = idx & 255;
        int m = m0 + mi, n = n0 + ni;
        float acc = 0.f;
        for (int k = 0; k < CHANNELS; k++)
            acc += __half2float(Araw[(size_t)m * CHANNELS + k]) *
                   __half2float(Wraw[(size_t)n * CHANNELS + k]);
        if (EPI == 0) {
            outp[(size_t)m * CHANNELS + n] = tanhf(acc + aux[n]);
        } else {
            int p = m >> 1, kb = m & 1;
            float hv = aux[(size_t)p * CHANNELS + n];
            outp[(size_t)p * 2048 + 2 * (size_t)n + kb] = (1.f - hv * hv) * acc;
        }
    }
#endif
}

// ---------------- host launcher ----------------
typedef CUresult (*tmap_encode_fn)(
    CUtensorMap*, CUtensorMapDataType, cuuint32_t, void*,
    const cuuint64_t*, const cuuint64_t*, const cuuint32_t*, const cuuint32_t*,
    CUtensorMapInterleave, CUtensorMapSwizzle, CUtensorMapL2promotion,
    CUtensorMapFloatOOBfill);

static void make_map2d(tmap_encode_fn enc, CUtensorMap* m, void* base, unsigned long long rows) {
    cuuint64_t dims[2]    = {(cuuint64_t)CHANNELS, (cuuint64_t)rows};
    cuuint64_t strides[1] = {(cuuint64_t)(CHANNELS * sizeof(__half))};
    cuuint32_t box[2]     = {64u, 256u};
    cuuint32_t es[2]      = {1u, 1u};
    enc(m, CU_TENSOR_MAP_DATA_TYPE_FLOAT16, 2, base, dims, strides, box, es,
        CU_TENSOR_MAP_INTERLEAVE_NONE, CU_TENSOR_MAP_SWIZZLE_128B,
        CU_TENSOR_MAP_L2_PROMOTION_L2_128B, CU_TENSOR_MAP_FLOAT_OOB_FILL_NONE);
}

extern "C" void kernel_launch(void* const* d_in, const int* in_sizes, int n_in,
                              void* d_out, int out_size)
{
    const float* x = (const float*)d_in[0];   // [3*PIVOT, CHANNELS]
    const float* W = (const float*)d_in[1];   // [CHANNELS, CHANNELS]
    const float* b = (const float*)d_in[2];   // [CHANNELS]
    float* out = (float*)d_out;

    void *pX = nullptr, *pW = nullptr, *pA2 = nullptr;
    cudaGetSymbolAddress(&pX,  Xh_g);
    cudaGetSymbolAddress(&pW,  Wh_g);
    cudaGetSymbolAddress(&pA2, A2_g);

    void* encp = nullptr;
    cudaDriverEntryPointQueryResult qr;
    cudaGetDriverEntryPoint("cuTensorMapEncodeTiled", &encp, cudaEnableDefault, &qr);
    tmap_encode_fn enc = (tmap_encode_fn)encp;

    CUtensorMap mX, mW, mA2;
    make_map2d(enc, &mX,  pX,  PIVOT);
    make_map2d(enc, &mW,  pW,  CHANNELS);
    make_map2d(enc, &mA2, pA2, 2 * PIVOT);

    cudaFuncSetAttribute(gemm_tma<0>, cudaFuncAttributeMaxDynamicSharedMemorySize, SMEM_TOTAL);
    cudaFuncSetAttribute(gemm_tma<1>, cudaFuncAttributeMaxDynamicSharedMemorySize, SMEM_TOTAL);

    const size_t NX = (size_t)PIVOT * CHANNELS / 4;
    const size_t NW = (size_t)CHANNELS * CHANNELS / 4;
    cvt_XW<<<(unsigned)((NX + NW) / 256), 256>>>(x, W);
    cvt_J<<<(unsigned)((size_t)PIVOT * 512 / 256), 256>>>(x + (size_t)PIVOT * CHANNELS);

    dim3 g1(CHANNELS / BN, PIVOT / BM);          // (4, 64)
    gemm_tma<0><<<g1, 256, SMEM_TOTAL>>>(mX, mW, (const __half*)pX, (const __half*)pW, b, out);

    dim3 g2(CHANNELS / BN, (2 * PIVOT) / BM);    // (4, 128)
    gemm_tma<1><<<g2, 256, SMEM_TOTAL>>>(mA2, mW, (const __half*)pA2, (const __half*)pW,
                                         out, out + (size_t)PIVOT * CHANNELS);
}